// round 15
// baseline (speedup 1.0000x reference)
#include <cuda_runtime.h>
#include <cuda_fp16.h>
#include <cstdint>

#define NNODES 40000
#define NEDGES_MAX 640000
#define NGRAPHS 128
#define DD 128

// ---------------- scratch (no allocations allowed) ----------------
__device__ __half g_t[(size_t)NNODES * DD];   // GEMM output (fp16 gather payload)
__device__ __half g_hf[(size_t)NNODES * DD];  // fp16 hidden state (GEMM input)
__device__ int    g_deg[NNODES];
__device__ int    g_rowptr[NNODES + 1];
__device__ int    g_cursor[NNODES];
__device__ int    g_partials[256];
__device__ int    g_esrc[NEDGES_MAX];
__device__ float  g_ewr[NEDGES_MAX];
// W fragments (fp16x2 packed — W quantized to fp16), fragment-ordered
__device__ uint32_t g_wfrag[3][8192];

// ======================= fp16 tensor GEMM (mma.sync m16n8k16) ============
// t[M,128] = A[M,128] @ fp16(W)[128,128]^T, A already fp16 (exact input).
// BM=64, 8 warps, warp tile 32x32, 4 CTAs/SM.

__device__ __forceinline__ uint32_t f16x2_pack(float even, float odd) {
    __half2 h = __float22half2_rn(make_float2(even, odd));  // .x = even (low half)
    return *reinterpret_cast<uint32_t*>(&h);
}

__device__ __forceinline__ void mma_f16(float* c, const uint32_t* a, const uint32_t* b) {
    asm volatile(
        "mma.sync.aligned.m16n8k16.row.col.f32.f16.f16.f32 "
        "{%0,%1,%2,%3}, {%4,%5,%6,%7}, {%8,%9}, {%0,%1,%2,%3};"
        : "+f"(c[0]), "+f"(c[1]), "+f"(c[2]), "+f"(c[3])
        : "r"(a[0]), "r"(a[1]), "r"(a[2]), "r"(a[3]), "r"(b[0]), "r"(b[1]));
}

__global__ __launch_bounds__(256, 4) void gemm_mma_kernel(
    const __half* __restrict__ A, const uint32_t* __restrict__ wf,
    __half* __restrict__ out, int M)
{
    __shared__ uint32_t smem[4096];      // 64 rows x 64 f16x2 = 16 KB
    const int tid  = threadIdx.x;
    const int wid  = tid >> 5;
    const int lane = tid & 31;
    const int wm   = wid >> 2;          // 0..1  (32-row group)
    const int wn   = wid & 3;           // 0..3  (32-col group)
    const int rbase = blockIdx.x * 64;

    float C[2][4][4];
    #pragma unroll
    for (int i = 0; i < 2; i++)
        #pragma unroll
        for (int j = 0; j < 4; j++)
            #pragma unroll
            for (int q = 0; q < 4; q++) C[i][j][q] = 0.f;

    // ---- stage A (64x128 fp16) into fragment-ordered SMEM (no conversion) ----
    #pragma unroll
    for (int rep = 0; rep < 4; rep++) {
        int idx = rep * 256 + tid;          // 0..1023
        int row = idx >> 4;                 // 0..63
        int qq  = idx & 15;                 // uint4 index (4 pairs = 8 fp16)
        int gr  = rbase + row;
        uint4 v = (gr < M)
            ? __ldg((const uint4*)(A + (size_t)gr * DD) + qq)
            : make_uint4(0u, 0u, 0u, 0u);
        int mblk = row >> 4, r = row & 15;
        int gid = r & 7, rb = r >> 3;
        uint32_t e[4] = {v.x, v.y, v.z, v.w};
        #pragma unroll
        for (int p = 0; p < 4; p++) {
            int c2 = qq * 4 + p;            // pair index 0..63
            int ks = c2 >> 3;
            int tf = c2 & 3;
            int ii = (((c2 >> 2) & 1) << 1) | rb;
            int slot = ((gid << 2) | tf) ^ ks;  // lane swizzle vs ks
            smem[((mblk * 8 + ks) * 32 + slot) * 4 + ii] = e[p];
        }
    }
    __syncthreads();

    // ---- 8 k16-steps of m16n8k16, single term ----
    #pragma unroll
    for (int ks = 0; ks < 8; ks++) {
        uint32_t Af[2][4], Bf[4][2];
        #pragma unroll
        for (int fm = 0; fm < 2; fm++) {
            int mblk = wm * 2 + fm;
            int base = ((mblk * 8 + ks) * 32 + (lane ^ ks)) * 4;
            uint4 h = *(const uint4*)(smem + base);
            Af[fm][0] = h.x; Af[fm][1] = h.y; Af[fm][2] = h.z; Af[fm][3] = h.w;
        }
        #pragma unroll
        for (int fn = 0; fn < 4; fn++) {
            int nblk = wn * 4 + fn;
            int boff = ((nblk * 8 + ks) * 32 + lane) * 2;
            uint2 h = __ldg((const uint2*)(wf + boff));
            Bf[fn][0] = h.x; Bf[fn][1] = h.y;
        }
        #pragma unroll
        for (int fm = 0; fm < 2; fm++)
            #pragma unroll
            for (int fn = 0; fn < 4; fn++)
                mma_f16(C[fm][fn], Af[fm], Bf[fn]);
    }

    // ---- epilogue: write C frags as fp16 ----
    #pragma unroll
    for (int fm = 0; fm < 2; fm++) {
        int row0 = rbase + wm * 32 + fm * 16 + (lane >> 2);
        #pragma unroll
        for (int fn = 0; fn < 4; fn++) {
            int col = wn * 32 + fn * 8 + (lane & 3) * 2;
            if (row0 < M)
                *(__half2*)(out + (size_t)row0 * DD + col) =
                    __float22half2_rn(make_float2(C[fm][fn][0], C[fm][fn][1]));
            if (row0 + 8 < M)
                *(__half2*)(out + (size_t)(row0 + 8) * DD + col) =
                    __float22half2_rn(make_float2(C[fm][fn][2], C[fm][fn][3]));
        }
    }
}

// ---------------- feat -> fp16 conversion (once) + deg zeroing ----------------
__global__ void aconv_kernel(const float* __restrict__ A,
                             __half* __restrict__ hf, int* __restrict__ deg, int M)
{
    int idx = blockIdx.x * blockDim.x + threadIdx.x;   // 0..M*32-1
    if (idx < M) deg[idx] = 0;
    if (idx >= M * 32) return;
    int row = idx >> 5;
    int q   = idx & 31;                                // float4 index
    float4 v = __ldg((const float4*)(A + (size_t)row * DD) + q);
    uint2 o = make_uint2(f16x2_pack(v.x, v.y), f16x2_pack(v.z, v.w));
    ((uint2*)(hf + (size_t)row * DD))[q] = o;
}

// ---------------- W fragment precompute (once) + hg zeroing ----------------
__global__ void wconv_kernel(const float* __restrict__ W0,
                             const float* __restrict__ W1,
                             const float* __restrict__ W2,
                             uint32_t* __restrict__ wf,   // [3][8192]
                             float* __restrict__ hg)      // 49152 floats
{
    int idx = blockIdx.x * blockDim.x + threadIdx.x;      // 0..49151
    if (idx < NGRAPHS * 3 * DD) hg[idx] = 0.f;
    if (idx >= 3 * 8192) return;
    int l   = idx >> 13;
    int rem = idx & 8191;
    int n   = rem >> 6;          // 0..127 (out feature)
    int t   = rem & 63;          // k-pair index, k = 2t
    const float* W = (l == 0) ? W0 : (l == 1) ? W1 : W2;
    float x0 = __ldg(W + (size_t)n * DD + 2 * t);
    float x1 = __ldg(W + (size_t)n * DD + 2 * t + 1);
    uint32_t hi = f16x2_pack(x0, x1);
    int ks  = t >> 3;
    int tf  = t & 3;
    int ii  = (t >> 2) & 1;
    int nblk = n >> 3, gid = n & 7;
    int lane = gid * 4 + tf;
    int off = ((nblk * 8 + ks) * 32 + lane) * 2 + ii;
    wf[l * 8192 + off] = hi;
}

// ---------------- CSR build: histogram + 2-level scan + reorder ----------------
__global__ void hist_kernel(const int* __restrict__ col, int* __restrict__ deg, int E)
{
    int e = blockIdx.x * blockDim.x + threadIdx.x;
    if (e < E) atomicAdd(&deg[col[e]], 1);
}

__global__ void block_sum_kernel(const int* __restrict__ deg, int* __restrict__ partials, int N)
{
    __shared__ int s[256];
    int i = blockIdx.x * 256 + threadIdx.x;
    s[threadIdx.x] = (i < N) ? deg[i] : 0;
    __syncthreads();
    for (int off = 128; off > 0; off >>= 1) {
        if (threadIdx.x < off) s[threadIdx.x] += s[threadIdx.x + off];
        __syncthreads();
    }
    if (threadIdx.x == 0) partials[blockIdx.x] = s[0];
}

__global__ void scan_partials_kernel(int* __restrict__ partials, int nb,
                                     int* __restrict__ rowptr, int N)
{
    __shared__ int s[256];
    int t = threadIdx.x;
    int d = (t < nb) ? partials[t] : 0;
    s[t] = d;
    __syncthreads();
    #pragma unroll
    for (int off = 1; off < 256; off <<= 1) {
        int v = (t >= off) ? s[t - off] : 0;
        __syncthreads();
        s[t] += v;
        __syncthreads();
    }
    if (t < nb) partials[t] = s[t] - d;     // exclusive
    if (t == 255) rowptr[N] = s[255];       // grand total = E
}

__global__ void chunk_scan_kernel(const int* __restrict__ deg,
                                  const int* __restrict__ partials,
                                  int* __restrict__ rowptr, int* __restrict__ cursor, int N)
{
    __shared__ int s[256];
    int t = threadIdx.x;
    int i = blockIdx.x * 256 + t;
    int d = (i < N) ? deg[i] : 0;
    s[t] = d;
    __syncthreads();
    #pragma unroll
    for (int off = 1; off < 256; off <<= 1) {
        int v = (t >= off) ? s[t - off] : 0;
        __syncthreads();
        s[t] += v;
        __syncthreads();
    }
    if (i < N) {
        int val = partials[blockIdx.x] + s[t] - d;   // exclusive global prefix
        rowptr[i] = val;
        cursor[i] = val;
    }
}

__global__ void fill_kernel(const int* __restrict__ row, const int* __restrict__ col,
                            const float* __restrict__ ew,
                            int* __restrict__ cursor,
                            int* __restrict__ esrc, float* __restrict__ ewr, int E)
{
    int e = blockIdx.x * blockDim.x + threadIdx.x;
    if (e >= E) return;
    int c = col[e];
    int p = atomicAdd(&cursor[c], 1);
    esrc[p] = row[e];
    ewr[p]  = ew[e];
}

// ---------------- fused aggregate (CSR fp16 gather) + PReLU + pool ----------------
// Serial edge loop with (src,w) prefetched ONE iteration ahead: removes the
// index-load -> gather 2-hop latency chain (only gather latency exposed).
__device__ __forceinline__ void red_add_v4(float* dst, float4 v) {
    asm volatile("red.global.add.v4.f32 [%0], {%1, %2, %3, %4};"
                 :: "l"(dst), "f"(v.x), "f"(v.y), "f"(v.z), "f"(v.w)
                 : "memory");
}

__global__ __launch_bounds__(256) void aggregate_pool_kernel(
    const __half* __restrict__ t, const int* __restrict__ rowptr,
    const int* __restrict__ esrc, const float* __restrict__ ewr,
    const float* __restrict__ aptr, const int* __restrict__ batch,
    float* __restrict__ hout, __half* __restrict__ hfout,
    float* __restrict__ hg, int N, int loff)
{
    int wid  = (blockIdx.x * blockDim.x + threadIdx.x) >> 5;
    int lane = threadIdx.x & 31;
    int n0 = wid * 4;
    if (n0 >= N) return;
    float alpha = __ldg(aptr);

    float4 run = make_float4(0.f, 0.f, 0.f, 0.f);
    int curg = -1;
    int nend = n0 + 4; if (nend > N) nend = N;

    for (int n = n0; n < nend; n++) {
        int jb = __ldg(rowptr + n);
        int je = __ldg(rowptr + n + 1);
        float4 acc = make_float4(0.f, 0.f, 0.f, 0.f);
        if (jb < je) {
            int   r = __ldg(esrc + jb);
            float w = __ldg(ewr + jb);
            for (int j = jb; j < je; j++) {
                int rn = 0; float wn = 0.f;
                if (j + 1 < je) {               // prefetch next edge's scalars
                    rn = __ldg(esrc + j + 1);
                    wn = __ldg(ewr + j + 1);
                }
                uint2 u = __ldg((const uint2*)(t + (size_t)r * DD) + lane);
                float2 f01 = __half22float2(*reinterpret_cast<__half2*>(&u.x));
                float2 f23 = __half22float2(*reinterpret_cast<__half2*>(&u.y));
                acc.x = fmaf(f01.x, w, acc.x);
                acc.y = fmaf(f01.y, w, acc.y);
                acc.z = fmaf(f23.x, w, acc.z);
                acc.w = fmaf(f23.y, w, acc.w);
                r = rn; w = wn;
            }
        }
        float4 p;
        p.x = acc.x >= 0.f ? acc.x : alpha * acc.x;
        p.y = acc.y >= 0.f ? acc.y : alpha * acc.y;
        p.z = acc.z >= 0.f ? acc.z : alpha * acc.z;
        p.w = acc.w >= 0.f ? acc.w : alpha * acc.w;
        if (hfout) {
            uint2 o = make_uint2(f16x2_pack(p.x, p.y), f16x2_pack(p.z, p.w));
            ((uint2*)(hfout + (size_t)n * DD))[lane] = o;
        } else {
            *(float4*)(hout + (size_t)n * DD + lane * 4) = p;
        }

        int g = __ldg(batch + n);
        if (g != curg) {
            if (curg >= 0)
                red_add_v4(hg + (size_t)curg * (3 * DD) + loff + lane * 4, run);
            curg = g;
            run = p;
        } else {
            run.x += p.x; run.y += p.y; run.z += p.z; run.w += p.w;
        }
    }
    if (curg >= 0)
        red_add_v4(hg + (size_t)curg * (3 * DD) + loff + lane * 4, run);
}

// ---------------- launch ----------------
extern "C" void kernel_launch(void* const* d_in, const int* in_sizes, int n_in,
                              void* d_out, int out_size)
{
    const float* feat  = (const float*)d_in[0];
    const float* ew    = (const float*)d_in[1];
    const float* W[3]  = {(const float*)d_in[2], (const float*)d_in[3], (const float*)d_in[4]};
    const float* a[3]  = {(const float*)d_in[5], (const float*)d_in[6], (const float*)d_in[7]};
    const int*   eidx  = (const int*)d_in[8];
    const int*   batch = (const int*)d_in[9];

    const int N = in_sizes[0] / DD;      // 40000
    const int E = in_sizes[1];           // 640000
    const int* rowp = eidx;
    const int* colp = eidx + E;

    float *ewr_ptr;
    __half *t_ptr, *hf_ptr;
    int *deg_ptr, *rowptr_ptr, *cursor_ptr, *partials_ptr, *esrc_ptr;
    uint32_t* wf_ptr;
    cudaGetSymbolAddress((void**)&t_ptr,       g_t);
    cudaGetSymbolAddress((void**)&hf_ptr,      g_hf);
    cudaGetSymbolAddress((void**)&deg_ptr,     g_deg);
    cudaGetSymbolAddress((void**)&rowptr_ptr,  g_rowptr);
    cudaGetSymbolAddress((void**)&cursor_ptr,  g_cursor);
    cudaGetSymbolAddress((void**)&partials_ptr,g_partials);
    cudaGetSymbolAddress((void**)&esrc_ptr,    g_esrc);
    cudaGetSymbolAddress((void**)&ewr_ptr,     g_ewr);
    cudaGetSymbolAddress((void**)&wf_ptr,      g_wfrag);

    float* h_out = (float*)d_out;                         // (N, 128)
    float* hg    = (float*)d_out + (size_t)N * DD;        // (128, 384)

    cudaStream_t s = 0;
    const int nb = (N + 255) / 256;      // 157 chunks
    const int gemm_blocks = (N + 63) / 64;
    const int agg_warps   = (N + 3) / 4;
    const int agg_blocks  = (agg_warps * 32 + 255) / 256;

    // Ordered so that launch #6 (ncu -s 5 -c 1) is the GEMM.
    wconv_kernel<<<(NGRAPHS * 3 * DD + 255) / 256, 256, 0, s>>>(
        W[0], W[1], W[2], wf_ptr, hg);                                              // 1 (also zeroes hg)
    aconv_kernel<<<(N * 32 + 255) / 256, 256, 0, s>>>(feat, hf_ptr, deg_ptr, N);    // 2 (also zeroes deg)
    hist_kernel<<<(E + 255) / 256, 256, 0, s>>>(colp, deg_ptr, E);                  // 3
    block_sum_kernel<<<nb, 256, 0, s>>>(deg_ptr, partials_ptr, N);                  // 4
    scan_partials_kernel<<<1, 256, 0, s>>>(partials_ptr, nb, rowptr_ptr, N);        // 5
    gemm_mma_kernel<<<gemm_blocks, 256, 0, s>>>(hf_ptr, wf_ptr, t_ptr, N);          // 6 <- profiled
    chunk_scan_kernel<<<nb, 256, 0, s>>>(deg_ptr, partials_ptr, rowptr_ptr, cursor_ptr, N); // 7
    fill_kernel<<<(E + 255) / 256, 256, 0, s>>>(rowp, colp, ew, cursor_ptr, esrc_ptr, ewr_ptr, E); // 8

    // layer 0: aggregate -> fp16 hidden
    aggregate_pool_kernel<<<agg_blocks, 256, 0, s>>>(
        t_ptr, rowptr_ptr, esrc_ptr, ewr_ptr, a[0], batch,
        nullptr, hf_ptr, hg, N, 0);                                                 // 9

    // layer 1
    gemm_mma_kernel<<<gemm_blocks, 256, 0, s>>>(hf_ptr, wf_ptr + 8192, t_ptr, N);
    aggregate_pool_kernel<<<agg_blocks, 256, 0, s>>>(
        t_ptr, rowptr_ptr, esrc_ptr, ewr_ptr, a[1], batch,
        nullptr, hf_ptr, hg, N, DD);

    // layer 2: aggregate -> fp32 d_out
    gemm_mma_kernel<<<gemm_blocks, 256, 0, s>>>(hf_ptr, wf_ptr + 16384, t_ptr, N);
    aggregate_pool_kernel<<<agg_blocks, 256, 0, s>>>(
        t_ptr, rowptr_ptr, esrc_ptr, ewr_ptr, a[2], batch,
        h_out, nullptr, hg, N, 2 * DD);
}

// round 17
// speedup vs baseline: 1.1732x; 1.1732x over previous
#include <cuda_runtime.h>
#include <cuda_fp16.h>
#include <cstdint>

#define NNODES 40000
#define NEDGES_MAX 640000
#define NGRAPHS 128
#define DD 128
#define NCHUNK 157

// ---------------- scratch (no allocations allowed) ----------------
__device__ __half g_t[(size_t)NNODES * DD];   // GEMM output (fp16 gather payload)
__device__ __half g_hf[(size_t)NNODES * DD];  // fp16 hidden state (GEMM input)
__device__ int    g_deg[NNODES];
__device__ int    g_rowptr[NNODES + 1];
__device__ int    g_cursor[NNODES];
__device__ unsigned g_scanstate[NCHUNK];      // (flag<<30)|value, 0 = invalid
__device__ int    g_esrc[NEDGES_MAX];
__device__ float  g_ewr[NEDGES_MAX];
// W fragments (fp16x2 packed — W quantized to fp16), fragment-ordered
__device__ uint32_t g_wfrag[3][8192];

// ======================= fp16 tensor GEMM (mma.sync m16n8k16) ============
// t[M,128] = A[M,128] @ fp16(W)[128,128]^T, A already fp16 (exact input).
// BM=64, 8 warps, warp tile 32x32, 4 CTAs/SM.  (R14 form — frozen)

__device__ __forceinline__ uint32_t f16x2_pack(float even, float odd) {
    __half2 h = __float22half2_rn(make_float2(even, odd));  // .x = even (low half)
    return *reinterpret_cast<uint32_t*>(&h);
}

__device__ __forceinline__ void mma_f16(float* c, const uint32_t* a, const uint32_t* b) {
    asm volatile(
        "mma.sync.aligned.m16n8k16.row.col.f32.f16.f16.f32 "
        "{%0,%1,%2,%3}, {%4,%5,%6,%7}, {%8,%9}, {%0,%1,%2,%3};"
        : "+f"(c[0]), "+f"(c[1]), "+f"(c[2]), "+f"(c[3])
        : "r"(a[0]), "r"(a[1]), "r"(a[2]), "r"(a[3]), "r"(b[0]), "r"(b[1]));
}

__global__ __launch_bounds__(256, 4) void gemm_mma_kernel(
    const __half* __restrict__ A, const uint32_t* __restrict__ wf,
    __half* __restrict__ out, int M)
{
    __shared__ uint32_t smem[4096];      // 64 rows x 64 f16x2 = 16 KB
    const int tid  = threadIdx.x;
    const int wid  = tid >> 5;
    const int lane = tid & 31;
    const int wm   = wid >> 2;          // 0..1  (32-row group)
    const int wn   = wid & 3;           // 0..3  (32-col group)
    const int rbase = blockIdx.x * 64;

    float C[2][4][4];
    #pragma unroll
    for (int i = 0; i < 2; i++)
        #pragma unroll
        for (int j = 0; j < 4; j++)
            #pragma unroll
            for (int q = 0; q < 4; q++) C[i][j][q] = 0.f;

    // ---- stage A (64x128 fp16) into fragment-ordered SMEM (no conversion) ----
    #pragma unroll
    for (int rep = 0; rep < 4; rep++) {
        int idx = rep * 256 + tid;          // 0..1023
        int row = idx >> 4;                 // 0..63
        int qq  = idx & 15;                 // uint4 index (4 pairs = 8 fp16)
        int gr  = rbase + row;
        uint4 v = (gr < M)
            ? __ldg((const uint4*)(A + (size_t)gr * DD) + qq)
            : make_uint4(0u, 0u, 0u, 0u);
        int mblk = row >> 4, r = row & 15;
        int gid = r & 7, rb = r >> 3;
        uint32_t e[4] = {v.x, v.y, v.z, v.w};
        #pragma unroll
        for (int p = 0; p < 4; p++) {
            int c2 = qq * 4 + p;            // pair index 0..63
            int ks = c2 >> 3;
            int tf = c2 & 3;
            int ii = (((c2 >> 2) & 1) << 1) | rb;
            int slot = ((gid << 2) | tf) ^ ks;  // lane swizzle vs ks
            smem[((mblk * 8 + ks) * 32 + slot) * 4 + ii] = e[p];
        }
    }
    __syncthreads();

    // ---- 8 k16-steps of m16n8k16, single term ----
    #pragma unroll
    for (int ks = 0; ks < 8; ks++) {
        uint32_t Af[2][4], Bf[4][2];
        #pragma unroll
        for (int fm = 0; fm < 2; fm++) {
            int mblk = wm * 2 + fm;
            int base = ((mblk * 8 + ks) * 32 + (lane ^ ks)) * 4;
            uint4 h = *(const uint4*)(smem + base);
            Af[fm][0] = h.x; Af[fm][1] = h.y; Af[fm][2] = h.z; Af[fm][3] = h.w;
        }
        #pragma unroll
        for (int fn = 0; fn < 4; fn++) {
            int nblk = wn * 4 + fn;
            int boff = ((nblk * 8 + ks) * 32 + lane) * 2;
            uint2 h = __ldg((const uint2*)(wf + boff));
            Bf[fn][0] = h.x; Bf[fn][1] = h.y;
        }
        #pragma unroll
        for (int fm = 0; fm < 2; fm++)
            #pragma unroll
            for (int fn = 0; fn < 4; fn++)
                mma_f16(C[fm][fn], Af[fm], Bf[fn]);
    }

    // ---- epilogue: write C frags as fp16 ----
    #pragma unroll
    for (int fm = 0; fm < 2; fm++) {
        int row0 = rbase + wm * 32 + fm * 16 + (lane >> 2);
        #pragma unroll
        for (int fn = 0; fn < 4; fn++) {
            int col = wn * 32 + fn * 8 + (lane & 3) * 2;
            if (row0 < M)
                *(__half2*)(out + (size_t)row0 * DD + col) =
                    __float22half2_rn(make_float2(C[fm][fn][0], C[fm][fn][1]));
            if (row0 + 8 < M)
                *(__half2*)(out + (size_t)(row0 + 8) * DD + col) =
                    __float22half2_rn(make_float2(C[fm][fn][2], C[fm][fn][3]));
        }
    }
}

// ---------------- feat -> fp16 conversion (once) + deg/scanstate zeroing ----------------
__global__ void aconv_kernel(const float* __restrict__ A,
                             __half* __restrict__ hf, int* __restrict__ deg,
                             unsigned* __restrict__ scanstate, int M)
{
    int idx = blockIdx.x * blockDim.x + threadIdx.x;   // 0..M*32-1
    if (idx < M) deg[idx] = 0;
    if (idx < NCHUNK) scanstate[idx] = 0u;
    if (idx >= M * 32) return;
    int row = idx >> 5;
    int q   = idx & 31;                                // float4 index
    float4 v = __ldg((const float4*)(A + (size_t)row * DD) + q);
    uint2 o = make_uint2(f16x2_pack(v.x, v.y), f16x2_pack(v.z, v.w));
    ((uint2*)(hf + (size_t)row * DD))[q] = o;
}

// ---------------- W fragment precompute (once) + hg zeroing ----------------
__global__ void wconv_kernel(const float* __restrict__ W0,
                             const float* __restrict__ W1,
                             const float* __restrict__ W2,
                             uint32_t* __restrict__ wf,   // [3][8192]
                             float* __restrict__ hg)      // 49152 floats
{
    int idx = blockIdx.x * blockDim.x + threadIdx.x;      // 0..49151
    if (idx < NGRAPHS * 3 * DD) hg[idx] = 0.f;
    if (idx >= 3 * 8192) return;
    int l   = idx >> 13;
    int rem = idx & 8191;
    int n   = rem >> 6;          // 0..127 (out feature)
    int t   = rem & 63;          // k-pair index, k = 2t
    const float* W = (l == 0) ? W0 : (l == 1) ? W1 : W2;
    float x0 = __ldg(W + (size_t)n * DD + 2 * t);
    float x1 = __ldg(W + (size_t)n * DD + 2 * t + 1);
    uint32_t hi = f16x2_pack(x0, x1);
    int ks  = t >> 3;
    int tf  = t & 3;
    int ii  = (t >> 2) & 1;
    int nblk = n >> 3, gid = n & 7;
    int lane = gid * 4 + tf;
    int off = ((nblk * 8 + ks) * 32 + lane) * 2 + ii;
    wf[l * 8192 + off] = hi;
}

// ---------------- CSR build: histogram + single-pass lookback scan + reorder ----------------
__global__ void hist_kernel(const int* __restrict__ col, int* __restrict__ deg, int E)
{
    int e = blockIdx.x * blockDim.x + threadIdx.x;
    if (e < E) atomicAdd(&deg[col[e]], 1);
}

// Decoupled-lookback exclusive scan over deg -> rowptr/cursor, one kernel.
// state[b] = (flag<<30)|value (UNSIGNED); flag 1 = aggregate, 2 = inclusive prefix.
__global__ void scan_kernel(const int* __restrict__ deg,
                            int* __restrict__ rowptr, int* __restrict__ cursor,
                            unsigned* __restrict__ state, int N, int nb)
{
    __shared__ int s[256];
    __shared__ int s_prefix;
    const int t = threadIdx.x;
    const int b = blockIdx.x;
    const int i = b * 256 + t;
    int d = (i < N) ? deg[i] : 0;
    s[t] = d;
    __syncthreads();
    #pragma unroll
    for (int off = 1; off < 256; off <<= 1) {
        int v = (t >= off) ? s[t - off] : 0;
        __syncthreads();
        s[t] += v;
        __syncthreads();
    }
    const int total = s[255];

    // publish: block 0 publishes its inclusive prefix immediately
    if (t == 0) {
        unsigned flag = (b == 0) ? 2u : 1u;
        __threadfence();
        atomicExch(&state[b], (flag << 30) | (unsigned)total);
    }

    // warp 0 performs lookback
    if (t < 32) {
        int prefix = 0;
        if (b > 0) {
            int look = b - 1;
            while (true) {
                int idx = look - t;
                unsigned st = (idx >= 0) ? atomicAdd(&state[idx], 0u) : (2u << 30);
                while (__any_sync(0xffffffffu, (st >> 30) == 0u)) {
                    if (idx >= 0 && (st >> 30) == 0u) st = atomicAdd(&state[idx], 0u);
                }
                unsigned pm = __ballot_sync(0xffffffffu, (st >> 30) == 2u);
                int firstp = __ffs(pm) - 1;                 // nearest inclusive prefix
                int val = (int)(st & 0x3fffffffu);
                int contrib = (pm == 0u || t <= firstp) ? val : 0;
                #pragma unroll
                for (int o = 16; o > 0; o >>= 1)
                    contrib += __shfl_down_sync(0xffffffffu, contrib, o);
                contrib = __shfl_sync(0xffffffffu, contrib, 0);
                prefix += contrib;
                if (pm) break;
                look -= 32;
            }
        }
        if (t == 0) {
            s_prefix = prefix;
            if (b > 0) {
                __threadfence();
                atomicExch(&state[b], (2u << 30) | (unsigned)(prefix + total));
            }
        }
    }
    __syncthreads();
    const int prefix = s_prefix;
    if (i < N) {
        int val = prefix + s[t] - d;     // exclusive global prefix
        rowptr[i] = val;
        cursor[i] = val;
    }
    if (b == nb - 1 && t == 0) rowptr[N] = prefix + total;   // = E
}

__global__ void fill_kernel(const int* __restrict__ row, const int* __restrict__ col,
                            const float* __restrict__ ew,
                            int* __restrict__ cursor,
                            int* __restrict__ esrc, float* __restrict__ ewr, int E)
{
    int e = blockIdx.x * blockDim.x + threadIdx.x;
    if (e >= E) return;
    int c = col[e];
    int p = atomicAdd(&cursor[c], 1);
    esrc[p] = row[e];
    ewr[p]  = ew[e];
}

// ---------------- fused aggregate (CSR fp16 gather) + PReLU + pool ----------------
// FROZEN R14 form: serial edge loop, 4 nodes/warp, no prefetch/unroll.
__device__ __forceinline__ void red_add_v4(float* dst, float4 v) {
    asm volatile("red.global.add.v4.f32 [%0], {%1, %2, %3, %4};"
                 :: "l"(dst), "f"(v.x), "f"(v.y), "f"(v.z), "f"(v.w)
                 : "memory");
}

__global__ __launch_bounds__(256) void aggregate_pool_kernel(
    const __half* __restrict__ t, const int* __restrict__ rowptr,
    const int* __restrict__ esrc, const float* __restrict__ ewr,
    const float* __restrict__ aptr, const int* __restrict__ batch,
    float* __restrict__ hout, __half* __restrict__ hfout,
    float* __restrict__ hg, int N, int loff)
{
    int wid  = (blockIdx.x * blockDim.x + threadIdx.x) >> 5;
    int lane = threadIdx.x & 31;
    int n0 = wid * 4;
    if (n0 >= N) return;
    float alpha = __ldg(aptr);

    float4 run = make_float4(0.f, 0.f, 0.f, 0.f);
    int curg = -1;
    int nend = n0 + 4; if (nend > N) nend = N;

    for (int n = n0; n < nend; n++) {
        int jb = __ldg(rowptr + n);
        int je = __ldg(rowptr + n + 1);
        float4 acc = make_float4(0.f, 0.f, 0.f, 0.f);
        for (int j = jb; j < je; j++) {
            int r   = __ldg(esrc + j);
            float w = __ldg(ewr + j);
            uint2 u = __ldg((const uint2*)(t + (size_t)r * DD) + lane);
            float2 f01 = __half22float2(*reinterpret_cast<__half2*>(&u.x));
            float2 f23 = __half22float2(*reinterpret_cast<__half2*>(&u.y));
            acc.x = fmaf(f01.x, w, acc.x);
            acc.y = fmaf(f01.y, w, acc.y);
            acc.z = fmaf(f23.x, w, acc.z);
            acc.w = fmaf(f23.y, w, acc.w);
        }
        float4 p;
        p.x = acc.x >= 0.f ? acc.x : alpha * acc.x;
        p.y = acc.y >= 0.f ? acc.y : alpha * acc.y;
        p.z = acc.z >= 0.f ? acc.z : alpha * acc.z;
        p.w = acc.w >= 0.f ? acc.w : alpha * acc.w;
        if (hfout) {
            uint2 o = make_uint2(f16x2_pack(p.x, p.y), f16x2_pack(p.z, p.w));
            ((uint2*)(hfout + (size_t)n * DD))[lane] = o;
        } else {
            *(float4*)(hout + (size_t)n * DD + lane * 4) = p;
        }

        int g = __ldg(batch + n);
        if (g != curg) {
            if (curg >= 0)
                red_add_v4(hg + (size_t)curg * (3 * DD) + loff + lane * 4, run);
            curg = g;
            run = p;
        } else {
            run.x += p.x; run.y += p.y; run.z += p.z; run.w += p.w;
        }
    }
    if (curg >= 0)
        red_add_v4(hg + (size_t)curg * (3 * DD) + loff + lane * 4, run);
}

// ---------------- launch ----------------
extern "C" void kernel_launch(void* const* d_in, const int* in_sizes, int n_in,
                              void* d_out, int out_size)
{
    const float* feat  = (const float*)d_in[0];
    const float* ew    = (const float*)d_in[1];
    const float* W[3]  = {(const float*)d_in[2], (const float*)d_in[3], (const float*)d_in[4]};
    const float* a[3]  = {(const float*)d_in[5], (const float*)d_in[6], (const float*)d_in[7]};
    const int*   eidx  = (const int*)d_in[8];
    const int*   batch = (const int*)d_in[9];

    const int N = in_sizes[0] / DD;      // 40000
    const int E = in_sizes[1];           // 640000
    const int* rowp = eidx;
    const int* colp = eidx + E;

    float *ewr_ptr;
    __half *t_ptr, *hf_ptr;
    int *deg_ptr, *rowptr_ptr, *cursor_ptr, *esrc_ptr;
    unsigned* state_ptr;
    uint32_t* wf_ptr;
    cudaGetSymbolAddress((void**)&t_ptr,       g_t);
    cudaGetSymbolAddress((void**)&hf_ptr,      g_hf);
    cudaGetSymbolAddress((void**)&deg_ptr,     g_deg);
    cudaGetSymbolAddress((void**)&rowptr_ptr,  g_rowptr);
    cudaGetSymbolAddress((void**)&cursor_ptr,  g_cursor);
    cudaGetSymbolAddress((void**)&state_ptr,   g_scanstate);
    cudaGetSymbolAddress((void**)&esrc_ptr,    g_esrc);
    cudaGetSymbolAddress((void**)&ewr_ptr,     g_ewr);
    cudaGetSymbolAddress((void**)&wf_ptr,      g_wfrag);

    float* h_out = (float*)d_out;                         // (N, 128)
    float* hg    = (float*)d_out + (size_t)N * DD;        // (128, 384)

    cudaStream_t s = 0;
    const int nb = (N + 255) / 256;      // 157 chunks
    const int gemm_blocks = (N + 63) / 64;
    const int agg_warps   = (N + 3) / 4;
    const int agg_blocks  = (agg_warps * 32 + 255) / 256;

    // Ordered so that launch #6 (ncu -s 5 -c 1) is the GEMM.
    wconv_kernel<<<(NGRAPHS * 3 * DD + 255) / 256, 256, 0, s>>>(
        W[0], W[1], W[2], wf_ptr, hg);                                              // 1 (zeroes hg)
    aconv_kernel<<<(N * 32 + 255) / 256, 256, 0, s>>>(
        feat, hf_ptr, deg_ptr, state_ptr, N);                                       // 2 (zeroes deg+state)
    hist_kernel<<<(E + 255) / 256, 256, 0, s>>>(colp, deg_ptr, E);                  // 3
    scan_kernel<<<nb, 256, 0, s>>>(deg_ptr, rowptr_ptr, cursor_ptr, state_ptr, N, nb); // 4
    fill_kernel<<<(E + 255) / 256, 256, 0, s>>>(rowp, colp, ew, cursor_ptr, esrc_ptr, ewr_ptr, E); // 5
    gemm_mma_kernel<<<gemm_blocks, 256, 0, s>>>(hf_ptr, wf_ptr, t_ptr, N);          // 6 <- profiled

    // layer 0: aggregate -> fp16 hidden
    aggregate_pool_kernel<<<agg_blocks, 256, 0, s>>>(
        t_ptr, rowptr_ptr, esrc_ptr, ewr_ptr, a[0], batch,
        nullptr, hf_ptr, hg, N, 0);                                                 // 7

    // layer 1
    gemm_mma_kernel<<<gemm_blocks, 256, 0, s>>>(hf_ptr, wf_ptr + 8192, t_ptr, N);
    aggregate_pool_kernel<<<agg_blocks, 256, 0, s>>>(
        t_ptr, rowptr_ptr, esrc_ptr, ewr_ptr, a[1], batch,
        nullptr, hf_ptr, hg, N, DD);

    // layer 2: aggregate -> fp32 d_out
    gemm_mma_kernel<<<gemm_blocks, 256, 0, s>>>(hf_ptr, wf_ptr + 16384, t_ptr, N);
    aggregate_pool_kernel<<<agg_blocks, 256, 0, s>>>(
        t_ptr, rowptr_ptr, esrc_ptr, ewr_ptr, a[2], batch,
        h_out, nullptr, hg, N, 2 * DD);
}